// round 16
// baseline (speedup 1.0000x reference)
#include <cuda_runtime.h>
#include <cuda_bf16.h>
#include <math.h>
#include <stdint.h>

typedef unsigned short u16;

// ---------------- problem constants ----------------
#define Bb    8
#define Cc    512
#define Tt    4096
#define CHK   16
#define CD    96
#define NBOOK 8
#define NEMB  1024
#define NCH   256
#define MR    (NCH*Bb*CHK)   // 32768
#define M2    (NCH*Bb)       // 2048

// ---------------- fp32 scratch ----------------
__device__ float g_pe[Cc*CHK];
__device__ float g_qln[CHK*Cc];
__device__ float g_Qc[CHK*Cc];
__device__ float g_cnorm[NBOOK*NEMB];
__device__ float g_K   [(size_t)MR*Cc];
__device__ float g_V   [(size_t)MR*Cc];
__device__ float g_y   [(size_t)MR*Cc];
__device__ float g_rD  [(size_t)MR*CD];
__device__ float g_zhat[(size_t)MR*Cc];
__device__ float g_prev[(size_t)M2*Cc];
__device__ float g_q0  [(size_t)M2*Cc];
__device__ float g_Q0  [(size_t)M2*Cc];
__device__ float g_y0  [(size_t)M2*Cc];
__device__ float g_rD0 [(size_t)M2*CD];
__device__ float g_zh0 [(size_t)M2*Cc];

// ---------------- bf16 hi/lo scratch (activations) ----------------
__device__ __align__(16) u16 u_qlnh[CHK*Cc],  u_qlnl[CHK*Cc];
__device__ __align__(16) u16 u_kvh [(size_t)MR*Cc],  u_kvl [(size_t)MR*Cc];
__device__ __align__(16) u16 u_ctxh[(size_t)MR*Cc],  u_ctxl[(size_t)MR*Cc];
__device__ __align__(16) u16 u_lnh [(size_t)MR*Cc],  u_lnl [(size_t)MR*Cc];
__device__ __align__(16) u16 u_hh  [(size_t)MR*2*Cc],u_hl  [(size_t)MR*2*Cc];
__device__ __align__(16) u16 u_xdh [(size_t)MR*Cc],  u_xdl [(size_t)MR*Cc];
__device__ __align__(16) u16 u_qdh [(size_t)MR*CD],  u_qdl [(size_t)MR*CD];
__device__ __align__(16) u16 u_q0h [(size_t)M2*Cc],  u_q0l [(size_t)M2*Cc];
__device__ __align__(16) u16 u_ctx0h[(size_t)M2*Cc], u_ctx0l[(size_t)M2*Cc];
__device__ __align__(16) u16 u_ln0h[(size_t)M2*Cc],  u_ln0l[(size_t)M2*Cc];
__device__ __align__(16) u16 u_h0h [(size_t)M2*2*Cc],u_h0l [(size_t)M2*2*Cc];
__device__ __align__(16) u16 u_xd0h[(size_t)M2*Cc],  u_xd0l[(size_t)M2*Cc];
__device__ __align__(16) u16 u_qd0h[(size_t)M2*CD],  u_qd0l[(size_t)M2*CD];

// ---------------- bf16 hi/lo weights (all stored [N][K]) ----------------
__device__ __align__(16) u16 w_qh[Cc*Cc],  w_ql[Cc*Cc];
__device__ __align__(16) u16 w_kh[Cc*Cc],  w_kl[Cc*Cc];
__device__ __align__(16) u16 w_vh[Cc*Cc],  w_vl[Cc*Cc];
__device__ __align__(16) u16 w_oh[Cc*Cc],  w_ol[Cc*Cc];
__device__ __align__(16) u16 w_1h[2*Cc*Cc],w_1l[2*Cc*Cc];
__device__ __align__(16) u16 w_2h[2*Cc*Cc],w_2l[2*Cc*Cc];
__device__ __align__(16) u16 w_dh[CD*Cc],  w_dl[CD*Cc];
__device__ __align__(16) u16 w_uh[Cc*CD],  w_ul[Cc*CD];
__device__ __align__(16) u16 bk_h[NBOOK*NEMB*CD], bk_l[NBOOK*NEMB*CD];

// ---------------- helpers ----------------
__device__ __forceinline__ float geluf(float x) {
    return 0.5f * x * (1.0f + erff(x * 0.70710678118654752440f));
}
__device__ __forceinline__ void split1(float v, u16& h, u16& l) {
    __nv_bfloat16 hb = __float2bfloat16(v);
    __nv_bfloat16 lb = __float2bfloat16(v - __bfloat162float(hb));
    h = __bfloat16_as_ushort(hb);
    l = __bfloat16_as_ushort(lb);
}
__device__ __forceinline__ void split2(float v0, float v1, uint32_t& hi, uint32_t& lo) {
    u16 h0, l0, h1, l1;
    split1(v0, h0, l0); split1(v1, h1, l1);
    hi = (uint32_t)h0 | ((uint32_t)h1 << 16);
    lo = (uint32_t)l0 | ((uint32_t)l1 << 16);
}
__device__ __forceinline__ uint32_t smem_u32(const void* p) {
    uint32_t a;
    asm("{ .reg .u64 t; cvta.to.shared.u64 t, %1; cvt.u32.u64 %0, t; }" : "=r"(a) : "l"(p));
    return a;
}
__device__ __forceinline__ void cpa16(uint32_t dst, const void* src, int sz) {
    asm volatile("cp.async.cg.shared.global [%0], [%1], 16, %2;"
                 :: "r"(dst), "l"(src), "r"(sz) : "memory");
}
__device__ __forceinline__ void mma_bf16(float* c, const uint32_t* a, const uint32_t* b) {
    asm volatile(
        "mma.sync.aligned.m16n8k16.row.col.f32.bf16.bf16.f32 "
        "{%0,%1,%2,%3}, {%4,%5,%6,%7}, {%8,%9}, {%0,%1,%2,%3};"
        : "+f"(c[0]), "+f"(c[1]), "+f"(c[2]), "+f"(c[3])
        : "r"(a[0]), "r"(a[1]), "r"(a[2]), "r"(a[3]), "r"(b[0]), "r"(b[1]));
}
__device__ __forceinline__ void ldsm4(uint32_t& r0, uint32_t& r1, uint32_t& r2,
                                      uint32_t& r3, uint32_t addr) {
    asm volatile("ldmatrix.sync.aligned.m8n8.x4.shared.b16 {%0,%1,%2,%3}, [%4];"
                 : "=r"(r0), "=r"(r1), "=r"(r2), "=r"(r3) : "r"(addr));
}

// ---------------- LN helper ----------------
__device__ __forceinline__ float2 block_ln2(float x0, float x1, int c0, int c1,
                                            const float* __restrict__ g,
                                            const float* __restrict__ b,
                                            float* red)
{
    int tid = threadIdx.x, lane = tid & 31, w = tid >> 5;
    float s = x0 + x1;
#pragma unroll
    for (int o = 16; o; o >>= 1) s += __shfl_xor_sync(0xffffffffu, s, o);
    if (lane == 0) red[w] = s;
    __syncthreads();
    float tot = 0.f;
#pragma unroll
    for (int i = 0; i < 8; i++) tot += red[i];
    float mean = tot * (1.0f / 512.0f);
    float d0 = x0 - mean, d1 = x1 - mean;
    float q = d0 * d0 + d1 * d1;
#pragma unroll
    for (int o = 16; o; o >>= 1) q += __shfl_xor_sync(0xffffffffu, q, o);
    __syncthreads();
    if (lane == 0) red[w] = q;
    __syncthreads();
    float tot2 = 0.f;
#pragma unroll
    for (int i = 0; i < 8; i++) tot2 += red[i];
    float inv = rsqrtf(tot2 * (1.0f / 512.0f) + 1e-5f);
    return make_float2(d0 * inv * g[c0] + b[c0], d1 * inv * g[c1] + b[c1]);
}

// ---------------- merged prep: splits + cnorm + pe/qln, ONE launch ----------
__global__ void prep_splits_k(const float* __restrict__ Wq, const float* __restrict__ Wk,
                              const float* __restrict__ Wv, const float* __restrict__ Wo,
                              const float* __restrict__ W1, const float* __restrict__ W2,
                              const float* __restrict__ Wd, const float* __restrict__ Wu,
                              const float* __restrict__ books,
                              const float* __restrict__ lnq_g,
                              const float* __restrict__ lnq_b)
{
    __shared__ float red[8];
    int b = blockIdx.x, tid = threadIdx.x;
    u16 h, l;
    if (b < 4096) {
        int e = b * 256 + tid;
        int w = e >> 18, idx = e & 262143;
        const float* W = (w == 0) ? Wq : (w == 1) ? Wk : (w == 2) ? Wv : Wo;
        u16* oh = (w == 0) ? w_qh : (w == 1) ? w_kh : (w == 2) ? w_vh : w_oh;
        u16* ol = (w == 0) ? w_ql : (w == 1) ? w_kl : (w == 2) ? w_vl : w_ol;
        int k = idx >> 9, n = idx & 511;
        split1(W[idx], h, l);
        oh[(size_t)n * 512 + k] = h;
        ol[(size_t)n * 512 + k] = l;
    } else if (b < 6144) {
        int e = (b - 4096) * 256 + tid;
        int k = e >> 10, n = e & 1023;
        split1(W1[e], h, l);
        w_1h[(size_t)n * 512 + k] = h;
        w_1l[(size_t)n * 512 + k] = l;
    } else if (b < 8192) {
        int e = (b - 6144) * 256 + tid;
        int k = e >> 9, n = e & 511;
        split1(W2[e], h, l);
        w_2h[(size_t)n * 1024 + k] = h;
        w_2l[(size_t)n * 1024 + k] = l;
    } else if (b < 8384) {
        int e = (b - 8192) * 256 + tid;
        split1(Wd[e], h, l); w_dh[e] = h; w_dl[e] = l;
    } else if (b < 8576) {
        int e = (b - 8384) * 256 + tid;
        split1(Wu[e], h, l); w_uh[e] = h; w_ul[e] = l;
    } else if (b < 11648) {
        int e = (b - 8576) * 256 + tid;
        split1(books[e], h, l); bk_h[e] = h; bk_l[e] = l;
    } else if (b < 11680) {
        int idx = (b - 11648) * 256 + tid;
        const float* e = books + (size_t)idx * CD;
        float s = 0.f;
#pragma unroll
        for (int d = 0; d < CD; d++) { float v = e[d]; s += v * v; }
        g_cnorm[idx] = 0.5f * s;
    } else {
        int t = b - 11680;
        int c0 = 2 * tid, c1 = c0 + 1;
        double dv = exp((double)c0 * (-log(10000.0) / 512.0));
        double ang = (double)t * dv;
        float v0 = (float)sin(ang);
        float v1 = (float)cos(ang);
        g_pe[c0 * CHK + t] = v0;
        g_pe[c1 * CHK + t] = v1;
        float2 y = block_ln2(v0, v1, c0, c1, lnq_g, lnq_b, red);
        g_qln[t * Cc + c0] = y.x;
        g_qln[t * Cc + c1] = y.y;
        split1(y.x, h, l); u_qlnh[t * Cc + c0] = h; u_qlnl[t * Cc + c0] = l;
        split1(y.y, h, l); u_qlnh[t * Cc + c1] = h; u_qlnl[t * Cc + c1] = l;
    }
}

// ---------------- prep kernels ----------------
__global__ void __launch_bounds__(256) kvln2_k(const float* __restrict__ qa,
                                               const float* __restrict__ g,
                                               const float* __restrict__ b)
{
    __shared__ float tile[16][513];
    int blk = blockIdx.x, tid = threadIdx.x;
    int s = blk >> 3, bb = blk & 7;
#pragma unroll
    for (int l = 0; l < 8; l++) {
        int e = tid + l * 256;
        int c = e >> 2, seg = e & 3;
        float4 v = *(const float4*)(qa + ((size_t)(bb * Cc + c)) * Tt + s * CHK + seg * 4);
        tile[seg * 4 + 0][c] = v.x;
        tile[seg * 4 + 1][c] = v.y;
        tile[seg * 4 + 2][c] = v.z;
        tile[seg * 4 + 3][c] = v.w;
    }
    __syncthreads();
    int w = tid >> 5, lane = tid & 31;
#pragma unroll
    for (int t = w; t < 16; t += 8) {
        int n = s * 128 + bb * 16 + t;
        float xs[16], sum = 0.f;
#pragma unroll
        for (int k = 0; k < 16; k++) {
            int c = lane + 32 * k;
            float x = tile[t][c] + g_pe[c * CHK + t];
            xs[k] = x; sum += x;
        }
#pragma unroll
        for (int o = 16; o; o >>= 1) sum += __shfl_xor_sync(0xffffffffu, sum, o);
        float mean = sum * (1.0f / 512.0f);
        float q = 0.f;
#pragma unroll
        for (int k = 0; k < 16; k++) { float d = xs[k] - mean; q += d * d; }
#pragma unroll
        for (int o = 16; o; o >>= 1) q += __shfl_xor_sync(0xffffffffu, q, o);
        float inv = rsqrtf(q * (1.0f / 512.0f) + 1e-5f);
#pragma unroll
        for (int k = 0; k < 16; k++) {
            int c = lane + 32 * k;
            float o2 = (xs[k] - mean) * inv * g[c] + b[c];
            u16 h, l2; split1(o2, h, l2);
            u_kvh[(size_t)n * Cc + c] = h;
            u_kvl[(size_t)n * Cc + c] = l2;
        }
    }
}

__global__ void ln_rows_k(const float* __restrict__ in, u16* __restrict__ oh,
                          u16* __restrict__ ol,
                          const float* __restrict__ g, const float* __restrict__ b)
{
    __shared__ float red[8];
    int n = blockIdx.x, tid = threadIdx.x;
    int c0 = tid, c1 = tid + 256;
    float x0 = in[(size_t)n * Cc + c0];
    float x1 = in[(size_t)n * Cc + c1];
    float2 y = block_ln2(x0, x1, c0, c1, g, b, red);
    u16 h, l;
    split1(y.x, h, l); oh[(size_t)n * Cc + c0] = h; ol[(size_t)n * Cc + c0] = l;
    split1(y.y, h, l); oh[(size_t)n * Cc + c1] = h; ol[(size_t)n * Cc + c1] = l;
}

__global__ void __launch_bounds__(256) residA2_k(const float* __restrict__ zt,
                                                 const float* __restrict__ y,
                                                 const float* __restrict__ g,
                                                 const float* __restrict__ b,
                                                 const float* __restrict__ scale)
{
    __shared__ float tile[16][513];
    int blk = blockIdx.x, tid = threadIdx.x;
    int s = blk >> 3, bb = blk & 7;
    float sc = fminf(fmaxf(scale[0], 0.005f), 0.5f);
#pragma unroll
    for (int l = 0; l < 8; l++) {
        int e = tid + l * 256;
        int c = e >> 2, seg = e & 3;
        float4 v = *(const float4*)(zt + ((size_t)(bb * Cc + c)) * Tt + s * CHK + seg * 4);
        tile[seg * 4 + 0][c] = v.x;
        tile[seg * 4 + 1][c] = v.y;
        tile[seg * 4 + 2][c] = v.z;
        tile[seg * 4 + 3][c] = v.w;
    }
    __syncthreads();
    int w = tid >> 5, lane = tid & 31;
#pragma unroll
    for (int t = w; t < 16; t += 8) {
        int n = s * 128 + bb * 16 + t;
        float xs[16], sum = 0.f;
#pragma unroll
        for (int k = 0; k < 16; k++) {
            int c = lane + 32 * k;
            float x = tile[t][c] - y[(size_t)n * Cc + c];
            xs[k] = x; sum += x;
        }
#pragma unroll
        for (int o = 16; o; o >>= 1) sum += __shfl_xor_sync(0xffffffffu, sum, o);
        float mean = sum * (1.0f / 512.0f);
        float q = 0.f;
#pragma unroll
        for (int k = 0; k < 16; k++) { float d = xs[k] - mean; q += d * d; }
#pragma unroll
        for (int o = 16; o; o >>= 1) q += __shfl_xor_sync(0xffffffffu, q, o);
        float inv = rsqrtf(q * (1.0f / 512.0f) + 1e-5f);
#pragma unroll
        for (int k = 0; k < 16; k++) {
            int c = lane + 32 * k;
            float o2 = sc * tanhf((xs[k] - mean) * inv * g[c] + b[c]);
            u16 h, l2; split1(o2, h, l2);
            u_xdh[(size_t)n * Cc + c] = h;
            u_xdl[(size_t)n * Cc + c] = l2;
        }
    }
}

__global__ void residB_k(const float* __restrict__ zt, const float* __restrict__ y,
                         const float* __restrict__ g, const float* __restrict__ b,
                         const float* __restrict__ scale)
{
    __shared__ float red[8];
    int n = blockIdx.x, tid = threadIdx.x;
    int s = n >> 3, bb = n & 7;
    int tg = s * CHK;
    float sc = fminf(fmaxf(scale[0], 0.005f), 0.5f);
    int c0 = tid, c1 = tid + 256;
    float x0 = zt[((size_t)(bb * Cc + c0)) * Tt + tg] - y[(size_t)n * Cc + c0];
    float x1 = zt[((size_t)(bb * Cc + c1)) * Tt + tg] - y[(size_t)n * Cc + c1];
    float2 o = block_ln2(x0, x1, c0, c1, g, b, red);
    u16 h, l;
    split1(sc * tanhf(o.x), h, l); u_xd0h[(size_t)n * Cc + c0] = h; u_xd0l[(size_t)n * Cc + c0] = l;
    split1(sc * tanhf(o.y), h, l); u_xd0h[(size_t)n * Cc + c1] = h; u_xd0l[(size_t)n * Cc + c1] = l;
}

__global__ void q0ln_k(const float* __restrict__ g, const float* __restrict__ b)
{
    __shared__ float red[8];
    int n = blockIdx.x, tid = threadIdx.x;
    int s = n >> 3;
    int c0 = tid, c1 = tid + 256;
    float p0 = (s > 0) ? g_prev[(size_t)(n - Bb) * Cc + c0] : 0.f;
    float p1 = (s > 0) ? g_prev[(size_t)(n - Bb) * Cc + c1] : 0.f;
    float x0 = p0 + g_pe[c0 * CHK + 0];
    float x1 = p1 + g_pe[c1 * CHK + 0];
    float2 y = block_ln2(x0, x1, c0, c1, g, b, red);
    g_q0[(size_t)n * Cc + c0] = y.x;
    g_q0[(size_t)n * Cc + c1] = y.y;
    u16 h, l;
    split1(y.x, h, l); u_q0h[(size_t)n * Cc + c0] = h; u_q0l[(size_t)n * Cc + c0] = l;
    split1(y.y, h, l); u_q0h[(size_t)n * Cc + c1] = h; u_q0l[(size_t)n * Cc + c1] = l;
}

__global__ void __launch_bounds__(256) scatterA2_k(const float* __restrict__ zhat,
                                                   float* __restrict__ out)
{
    __shared__ float tile[16][513];
    int blk = blockIdx.x, tid = threadIdx.x;
    int s = blk >> 3, bb = blk & 7;
    int n0 = s * 128 + bb * 16;
#pragma unroll
    for (int l = 0; l < 32; l++) {
        int e = tid + l * 256;
        int t = e >> 9, c = e & 511;
        float v = zhat[((size_t)(n0 + t)) * Cc + c];
        tile[t][c] = v;
        if (t == 15) g_prev[(size_t)(s * 8 + bb) * Cc + c] = v;
    }
    __syncthreads();
#pragma unroll
    for (int l = 0; l < 8; l++) {
        int e = tid + l * 256;
        int c = e >> 2, seg = e & 3;
        float4 v = make_float4(tile[seg * 4 + 0][c], tile[seg * 4 + 1][c],
                               tile[seg * 4 + 2][c], tile[seg * 4 + 3][c]);
        *(float4*)(out + ((size_t)(bb * Cc + c)) * Tt + s * CHK + seg * 4) = v;
    }
}

// ---------------- split-bf16 GEMM ----------------
__device__ __forceinline__ void gb_stage(uint32_t sbase,
    const u16* __restrict__ Ah, const u16* __restrict__ Al,
    const u16* __restrict__ Bh, const u16* __restrict__ Bl,
    int m0, int n0, int M, int N, int K, int k0, int tid)
{
#pragma unroll
    for (int l = 0; l < 2; l++) {
        int e = tid + l * 256;
        int row = e >> 2, seg = e & 3;
        uint32_t d = sbase + row * 80 + seg * 16;
        size_t oa = (size_t)(m0 + row) * K + k0 + seg * 8;
        int szA = (m0 + row < M) ? 16 : 0;
        cpa16(d,         Ah + oa, szA);
        cpa16(d + 10240, Al + oa, szA);
        size_t ob = (size_t)(n0 + row) * K + k0 + seg * 8;
        int szB = (n0 + row < N) ? 16 : 0;
        cpa16(d + 20480, Bh + ob, szB);
        cpa16(d + 30720, Bl + ob, szB);
    }
    asm volatile("cp.async.commit_group;" ::: "memory");
}

template<int NS>
__global__ void __launch_bounds__(256) gemm_b_k(
    const u16* __restrict__ Ah, const u16* __restrict__ Al,
    const u16* __restrict__ Bh, const u16* __restrict__ Bl,
    float* __restrict__ Cm, u16* __restrict__ Chi, u16* __restrict__ Clo,
    const float* __restrict__ bias, const float* __restrict__ resid,
    int M, int N, int K, int act, int rmode,
    const u16* __restrict__ Bh2, const u16* __restrict__ Bl2,
    float* __restrict__ Cm2,
    const u16* __restrict__ Ah3, const u16* __restrict__ Al3,
    const u16* __restrict__ Bh3, const u16* __restrict__ Bl3,
    float* __restrict__ Cm3, int M3, int omode)
{
    extern __shared__ char smem[];
    uint32_t sb = smem_u32(smem);
    int tid = threadIdx.x, wid = tid >> 5, lane = tid & 31;
    int g = lane >> 2, tg = lane & 3;
    int wm = (wid >> 2) * 64, wn = (wid & 3) * 32;
    int m0 = blockIdx.y * 128, n0 = blockIdx.x * 128;

    const u16 *Ahp = Ah, *Alp = Al, *Bhp = Bh, *Blp = Bl;
    float* Cmp = Cm;
    if (blockIdx.z == 1) { Bhp = Bh2; Blp = Bl2; Cmp = Cm2; }
    else if (blockIdx.z == 2) {
        Ahp = Ah3; Alp = Al3; Bhp = Bh3; Blp = Bl3; Cmp = Cm3; M = M3;
        if (m0 >= M) return;
    }

    float acc[4][4][4];
#pragma unroll
    for (int i = 0; i < 4; i++)
#pragma unroll
        for (int j = 0; j < 4; j++)
#pragma unroll
            for (int r = 0; r < 4; r++) acc[i][j][r] = 0.f;

    uint32_t aOffH = (uint32_t)(wm + (lane & 15)) * 80 + ((lane >> 4) & 1) * 16;
    uint32_t aOffL = aOffH + 10240;
    uint32_t bOffH = 20480u + (uint32_t)(wn + ((lane >> 4) & 1) * 8 + (lane & 7)) * 80
                   + ((lane >> 3) & 1) * 16;
    uint32_t bOffL = bOffH + 10240;

    int nch = K >> 5;
#pragma unroll
    for (int s = 0; s < NS - 1; s++) {
        if (s < nch)
            gb_stage(sb + s * 40960, Ahp, Alp, Bhp, Blp, m0, n0, M, N, K, s * 32, tid);
        else
            asm volatile("cp.async.commit_group;" ::: "memory");
    }

    for (int c = 0; c < nch; c++) {
        if (NS == 2) asm volatile("cp.async.wait_group 0;" ::: "memory");
        else         asm volatile("cp.async.wait_group 2;" ::: "memory");
        __syncthreads();
        int nx = c + NS - 1;
        if (nx < nch)
            gb_stage(sb + (nx & (NS - 1)) * 40960, Ahp, Alp, Bhp, Blp,
                     m0, n0, M, N, K, nx * 32, tid);
        else
            asm volatile("cp.async.commit_group;" ::: "memory");

        uint32_t sbuf = sb + (c & (NS - 1)) * 40960;
#pragma unroll
        for (int ks = 0; ks < 2; ks++) {
            uint32_t kb = ks * 32;
            uint32_t bh[4][2], bl[4][2];
#pragma unroll
            for (int nfp = 0; nfp < 2; nfp++) {
                ldsm4(bh[2*nfp][0], bh[2*nfp][1], bh[2*nfp+1][0], bh[2*nfp+1][1],
                      sbuf + bOffH + nfp * 1280 + kb);
                ldsm4(bl[2*nfp][0], bl[2*nfp][1], bl[2*nfp+1][0], bl[2*nfp+1][1],
                      sbuf + bOffL + nfp * 1280 + kb);
            }
#pragma unroll
            for (int mf = 0; mf < 4; mf++) {
                uint32_t ah[4], al[4];
                ldsm4(ah[0], ah[1], ah[2], ah[3], sbuf + aOffH + mf * 1280 + kb);
                ldsm4(al[0], al[1], al[2], al[3], sbuf + aOffL + mf * 1280 + kb);
#pragma unroll
                for (int nf = 0; nf < 4; nf++) {
                    mma_bf16(acc[mf][nf], ah, bl[nf]);
                    mma_bf16(acc[mf][nf], al, bh[nf]);
                    mma_bf16(acc[mf][nf], ah, bh[nf]);
                }
            }
        }
    }

#pragma unroll
    for (int mf = 0; mf < 4; mf++) {
        int mA = m0 + wm + mf * 16 + g;
#pragma unroll
        for (int nf = 0; nf < 4; nf++) {
            int nc = n0 + wn + nf * 8 + 2 * tg;
#pragma unroll
            for (int half = 0; half < 2; half++) {
                int m = mA + half * 8;
                if (m >= M) continue;
#pragma unroll
                for (int jj = 0; jj < 2; jj++) {
                    int nn = nc + jj;
                    if (nn >= N) continue;
                    float v = acc[mf][nf][half * 2 + jj];
                    if (bias)  v += bias[nn];
                    if (rmode == 1) v += resid[(size_t)m * N + nn];
                    else if (rmode == 2) v += resid[(size_t)(m & 15) * 512 + nn];
                    if (act == 1) v = geluf(v);
                    if (Chi) {
                        u16 h, l; split1(v, h, l);
                        Chi[(size_t)m * N + nn] = h;
                        Clo[(size_t)m * N + nn] = l;
                    } else if (omode == 2) {
                        Cmp[((size_t)((m & 7) * Cc + nn)) * Tt + (m >> 3) * CHK] = v;
                    } else {
                        Cmp[(size_t)m * N + nn] = v;
                    }
                }
            }
        }
    }
}

// ---------------- attention (float4-vectorized L1 traffic, bit-identical) ---
__global__ void __launch_bounds__(256) attnA_k(const float* __restrict__ Kmat,
                                               const float* __restrict__ Vmat)
{
    __shared__ float sKV[16][516];   // 516: rows 16B-aligned for LDS.128
    __shared__ float sS[16 * 8 * 16];
    int blk = blockIdx.x, tid = threadIdx.x;
    size_t n0 = (size_t)blk * CHK;

    // K fill (float4)
#pragma unroll
    for (int l = 0; l < 8; l++) {
        int e = tid + l * 256;            // 0..2047 = row*128 + c4
        int row = e >> 7, c4 = (e & 127) << 2;
        float4 v = *(const float4*)(Kmat + (n0 + row) * Cc + c4);
        *(float4*)&sKV[row][c4] = v;
    }
    __syncthreads();
    { // scores: thread = (t,k); float4 loads, scalar-order accumulation
        int t = tid >> 4, k = tid & 15;
        const float4* qrow = (const float4*)(g_Qc + t * Cc);
#pragma unroll
        for (int h = 0; h < 8; h++) {
            float s = 0.f;
            const float4* kp = (const float4*)&sKV[k][h * 64];
            const float4* qp = qrow + h * 16;
#pragma unroll
            for (int d4 = 0; d4 < 16; d4++) {
                float4 q = qp[d4], kk = kp[d4];
                s = fmaf(q.x, kk.x, s);
                s = fmaf(q.y, kk.y, s);
                s = fmaf(q.z, kk.z, s);
                s = fmaf(q.w, kk.w, s);
            }
            sS[(t * 8 + h) * 16 + k] = s * 0.125f;
        }
    }
    __syncthreads();
    if (tid < 128) {
        float* p = &sS[tid * 16];
        float m = p[0];
#pragma unroll
        for (int k = 1; k < 16; k++) m = fmaxf(m, p[k]);
        float sum = 0.f;
#pragma unroll
        for (int k = 0; k < 16; k++) { float e = expf(p[k] - m); p[k] = e; sum += e; }
        float inv = 1.0f / sum;
#pragma unroll
        for (int k = 0; k < 16; k++) p[k] *= inv;
    }
    __syncthreads();
    // V fill (float4)
#pragma unroll
    for (int l = 0; l < 8; l++) {
        int e = tid + l * 256;
        int row = e >> 7, c4 = (e & 127) << 2;
        float4 v = *(const float4*)(Vmat + (n0 + row) * Cc + c4);
        *(float4*)&sKV[row][c4] = v;
    }
    __syncthreads();
#pragma unroll
    for (int cc = 0; cc < 2; cc++) {
        int c = tid + cc * 256;
        int h = c >> 6;
#pragma unroll
        for (int t = 0; t < 16; t++) {
            float a = 0.f;
            const float* at = &sS[(t * 8 + h) * 16];
#pragma unroll
            for (int k = 0; k < 16; k++) a = fmaf(at[k], sKV[k][c], a);
            u16 hh, ll; split1(a, hh, ll);
            u_ctxh[(n0 + t) * Cc + c] = hh;
            u_ctxl[(n0 + t) * Cc + c] = ll;
        }
    }
}

__global__ void __launch_bounds__(256) attnB_k(const float* __restrict__ Kmat,
                                               const float* __restrict__ Vmat)
{
    __shared__ float sKV[16][516];
    __shared__ float sS[8 * 16];
    int blk = blockIdx.x, tid = threadIdx.x;
    size_t n0 = (size_t)blk * CHK;

#pragma unroll
    for (int l = 0; l < 8; l++) {
        int e = tid + l * 256;
        int row = e >> 7, c4 = (e & 127) << 2;
        float4 v = *(const float4*)(Kmat + (n0 + row) * Cc + c4);
        *(float4*)&sKV[row][c4] = v;
    }
    __syncthreads();
    if (tid < 128) {
        int h = tid >> 4, k = tid & 15;
        const float4* qp = (const float4*)(g_Q0 + (size_t)blk * Cc + h * 64);
        const float4* kp = (const float4*)&sKV[k][h * 64];
        float s = 0.f;
#pragma unroll
        for (int d4 = 0; d4 < 16; d4++) {
            float4 q = qp[d4], kk = kp[d4];
            s = fmaf(q.x, kk.x, s);
            s = fmaf(q.y, kk.y, s);
            s = fmaf(q.z, kk.z, s);
            s = fmaf(q.w, kk.w, s);
        }
        sS[h * 16 + k] = s * 0.125f;
    }
    __syncthreads();
    if (tid < 8) {
        float* p = &sS[tid * 16];
        float m = p[0];
#pragma unroll
        for (int k = 1; k < 16; k++) m = fmaxf(m, p[k]);
        float sum = 0.f;
#pragma unroll
        for (int k = 0; k < 16; k++) { float e = expf(p[k] - m); p[k] = e; sum += e; }
        float inv = 1.0f / sum;
#pragma unroll
        for (int k = 0; k < 16; k++) p[k] *= inv;
    }
    __syncthreads();
#pragma unroll
    for (int l = 0; l < 8; l++) {
        int e = tid + l * 256;
        int row = e >> 7, c4 = (e & 127) << 2;
        float4 v = *(const float4*)(Vmat + (n0 + row) * Cc + c4);
        *(float4*)&sKV[row][c4] = v;
    }
    __syncthreads();
#pragma unroll
    for (int cc = 0; cc < 2; cc++) {
        int c = tid + cc * 256;
        int h = c >> 6;
        float a = 0.f;
        const float* at = &sS[h * 16];
#pragma unroll
        for (int k = 0; k < 16; k++) a = fmaf(at[k], sKV[k][c], a);
        u16 hh, ll; split1(a, hh, ll);
        u_ctx0h[(size_t)blk * Cc + c] = hh;
        u_ctx0l[(size_t)blk * Cc + c] = ll;
    }
}

// ---------------- residual VQ ----------------
#define RVQ_SMEM 109568

__device__ __forceinline__ void rvq_prefetch(uint32_t sb, uint32_t dBh, uint32_t dBl,
    const u16* __restrict__ bkh, const u16* __restrict__ bkl,
    float* sHNbuf, int k, int ct, int tid)
{
    const u16* srcH = bkh + ((size_t)k * NEMB + ct * 64) * CD;
    const u16* srcL = bkl + ((size_t)k * NEMB + ct * 64) * CD;
#pragma unroll
    for (int l = 0; l < 3; l++) {
        int e = tid + l * 256;
        int c = e / 12, s2 = e - c * 12;
        cpa16(sb + dBh + c * 208 + s2 * 16, srcH + c * 96 + s2 * 8, 16);
        cpa16(sb + dBl + c * 208 + s2 * 16, srcL + c * 96 + s2 * 8, 16);
    }
    asm volatile("cp.async.commit_group;" ::: "memory");
    if (tid < 64) sHNbuf[tid] = g_cnorm[k * NEMB + ct * 64 + tid];
}

__global__ void __launch_bounds__(256) rvq_k(const float* __restrict__ rD,
                                             u16* __restrict__ qh, u16* __restrict__ ql,
                                             const float* __restrict__ books,
                                             const u16* __restrict__ bkh,
                                             const u16* __restrict__ bkl)
{
    extern __shared__ char sm[];
    float* sRes  = (float*)sm;
    uint32_t sb  = smem_u32(sm);
    const uint32_t oAh = 24832, oAl = 38144;
    const uint32_t oBhArr[2] = { 51456, 78080 };
    const uint32_t oBlArr[2] = { 64768, 91392 };
    float* sHN    = (float*)(sm + 104704);
    float* sScore = (float*)(sm + 105216);
    int*   sIdx   = (int*)  (sm + 107264);
    int*   sBest  = (int*)  (sm + 109312);

    int tid = threadIdx.x, wid = tid >> 5, lane = tid & 31;
    int g = lane >> 2, tg = lane & 3;
    int m0 = blockIdx.x * 64;

    for (int e = tid; e < 64 * 96; e += 256) {
        int r = e / 96, d = e - r * 96;
        sRes[r * 97 + d] = rD[(size_t)(m0 + r) * CD + d];
    }

    uint32_t aoff = (uint32_t)(lane & 15) * 208 + ((lane >> 4) & 1) * 16;
    uint32_t boff = (uint32_t)(wid * 8 + (lane & 7)) * 208 + ((lane >> 3) & 3) * 16;

    for (int k = 0; k < NBOOK; k++) {
        __syncthreads();
        rvq_prefetch(sb, oBhArr[0], oBlArr[0], bkh, bkl, sHN + 0, k, 0, tid);
        for (int e = tid; e < 64 * 48; e += 256) {
            int r = e / 48, w = e - r * 48;
            float v0 = sRes[r * 97 + 2 * w], v1 = sRes[r * 97 + 2 * w + 1];
            uint32_t hi, lo; split2(v0, v1, hi, lo);
            *(uint32_t*)(sm + oAh + r * 208 + w * 4) = hi;
            *(uint32_t*)(sm + oAl + r * 208 + w * 4) = lo;
        }
        float best[8]; int bidx[8];
#pragma unroll
        for (int s = 0; s < 8; s++) { best[s] = -3.0e38f; bidx[s] = 0x7fffffff; }

        for (int ct = 0; ct < 16; ct++) {
            int buf = ct & 1;
            if (ct + 1 < 16) {
                rvq_prefetch(sb, oBhArr[buf ^ 1], oBlArr[buf ^ 1], bkh, bkl,
                             sHN + 64 * (buf ^ 1), k, ct + 1, tid);
                asm volatile("cp.async.wait_group 1;" ::: "memory");
            } else {
                asm volatile("cp.async.wait_group 0;" ::: "memory");
            }
            __syncthreads();

            const uint32_t oBh = oBhArr[buf], oBl = oBlArr[buf];
            const float* sHNb = sHN + 64 * buf;

            float acc[4][4];
#pragma unroll
            for (int i = 0; i < 4; i++)
#pragma unroll
                for (int j = 0; j < 4; j++) acc[i][j] = 0.f;

#pragma unroll
            for (int kcp = 0; kcp < 3; kcp++) {
                uint32_t bhv[4], blv[4];
                ldsm4(bhv[0], bhv[1], bhv[2], bhv[3], sb + oBh + boff + kcp * 64);
                ldsm4(blv[0], blv[1], blv[2], blv[3], sb + oBl + boff + kcp * 64);
#pragma unroll
                for (int sub = 0; sub < 2; sub++) {
                    uint32_t bh2[2] = { bhv[sub * 2], bhv[sub * 2 + 1] };
                    uint32_t bl2[2] = { blv[sub * 2], blv[sub * 2 + 1] };
                    uint32_t ka = (uint32_t)(kcp * 2 + sub) * 32;
#pragma unroll
                    for (int mf = 0; mf < 4; mf++) {
                        uint32_t ah4[4], al4[4];
                        ldsm4(ah4[0], ah4[1], ah4[2], ah4[3],
                              sb + oAh + aoff + (uint32_t)mf * 16 * 208 + ka);
                        ldsm4(al4[0], al4[1], al4[2], al4[3],
                              sb + oAl + aoff + (uint32_t)mf * 16 * 208 + ka);
                        mma_bf16(acc[mf], ah4, bl2);
                        mma_bf16(acc[mf], al4, bh2);
                        mma_bf16(acc[mf], ah4, bh2);
                    }
                }
            }
#pragma unroll
            for (int mf = 0; mf < 4; mf++)
#pragma unroll
                for (int h = 0; h < 2; h++) {
                    int s = mf * 2 + h;
#pragma unroll
                    for (int j = 0; j < 2; j++) {
                        int cl = wid * 8 + 2 * tg + j;
                        float sc = acc[mf][h * 2 + j] - sHNb[cl];
                        int code = ct * 64 + cl;
                        if (sc > best[s] || (sc == best[s] && code < bidx[s])) {
                            best[s] = sc; bidx[s] = code;
                        }
                    }
                }
            __syncthreads();
        }
#pragma unroll
        for (int s = 0; s < 8; s++) {
#pragma unroll
            for (int off = 1; off <= 2; off <<= 1) {
                float os = __shfl_xor_sync(0xffffffffu, best[s], off);
                int   oi = __shfl_xor_sync(0xffffffffu, bidx[s], off);
                if (os > best[s] || (os == best[s] && oi < bidx[s])) {
                    best[s] = os; bidx[s] = oi;
                }
            }
        }
        if (tg == 0) {
#pragma unroll
            for (int mf = 0; mf < 4; mf++)
#pragma unroll
                for (int h = 0; h < 2; h++) {
                    int r = mf * 16 + 8 * h + g;
                    sScore[r * 8 + wid] = best[mf * 2 + h];
                    sIdx[r * 8 + wid]   = bidx[mf * 2 + h];
                }
        }
        __syncthreads();
        if (tid < 64) {
            float bs = -3.0e38f; int bi = 0x7fffffff;
#pragma unroll
            for (int w = 0; w < 8; w++) {
                float s2 = sScore[tid * 8 + w]; int ii = sIdx[tid * 8 + w];
                if (s2 > bs || (s2 == bs && ii < bi)) { bs = s2; bi = ii; }
            }
            sBest[tid] = bi;
        }
        __syncthreads();
        const float* bkb = books + (size_t)k * NEMB * CD;
        for (int e = tid; e < 64 * 96; e += 256) {
            int r = e / 96, d = e - r * 96;
            sRes[r * 97 + d] -= bkb[(size_t)sBest[r] * CD + d];
        }
    }
    __syncthreads();
    for (int e = tid; e < 64 * 96; e += 256) {
        int r = e / 96, d = e - r * 96;
        float v = rD[(size_t)(m0 + r) * CD + d] - sRes[r * 97 + d];
        u16 h, l; split1(v, h, l);
        qh[(size_t)(m0 + r) * CD + d] = h;
        ql[(size_t)(m0 + r) * CD + d] = l;
    }
}

// ---------------- host side ----------------
template<typename T>
static T* sym(const void* s) { void* p = nullptr; cudaGetSymbolAddress(&p, s); return (T*)p; }

static void gemmb(const u16* Ah, const u16* Al, const u16* Bh, const u16* Bl,
                  float* Cm, u16* Chi, u16* Clo,
                  const float* bias, const float* resid,
                  int M, int N, int K, int act, int rmode,
                  const u16* Bh2 = nullptr, const u16* Bl2 = nullptr,
                  float* Cm2 = nullptr,
                  const u16* Ah3 = nullptr, const u16* Al3 = nullptr,
                  const u16* Bh3 = nullptr, const u16* Bl3 = nullptr,
                  float* Cm3 = nullptr, int M3 = 0)
{
    static bool attr = false;
    if (!attr) {
        cudaFuncSetAttribute(gemm_b_k<2>, cudaFuncAttributeMaxDynamicSharedMemorySize,
                             2 * 40960);
        attr = true;
    }
    int zd = Ah3 ? 3 : (Bh2 ? 2 : 1);
    dim3 grid((N + 127) / 128, (M + 127) / 128, zd);
    gemm_b_k<2><<<grid, 256, 2 * 40960>>>(Ah, Al, Bh, Bl, Cm, Chi, Clo, bias, resid,
                                          M, N, K, act, rmode, Bh2, Bl2, Cm2,
                                          Ah3, Al3, Bh3, Bl3, Cm3, M3, 0);
}

static void gemmb4(const u16* Ah, const u16* Al, const u16* Bh, const u16* Bl,
                   float* Cm, u16* Chi, u16* Clo,
                   const float* bias, const float* resid,
                   int M, int N, int K, int act, int rmode, int omode = 0)
{
    static bool attr = false;
    if (!attr) {
        cudaFuncSetAttribute(gemm_b_k<4>, cudaFuncAttributeMaxDynamicSharedMemorySize,
                             4 * 40960);
        attr = true;
    }
    dim3 grid((N + 127) / 128, (M + 127) / 128, 1);
    gemm_b_k<4><<<grid, 256, 4 * 40960>>>(Ah, Al, Bh, Bl, Cm, Chi, Clo, bias, resid,
                                          M, N, K, act, rmode,
                                          nullptr, nullptr, nullptr,
                                          nullptr, nullptr, nullptr, nullptr,
                                          nullptr, 0, omode);
}

extern "C" void kernel_launch(void* const* d_in, const int* in_sizes, int n_in,
                              void* d_out, int out_size)
{
    const float* qa    = (const float*)d_in[0];
    const float* zt    = (const float*)d_in[1];
    const float* lnq_g = (const float*)d_in[2];
    const float* lnq_b = (const float*)d_in[3];
    const float* lnkv_g= (const float*)d_in[4];
    const float* lnkv_b= (const float*)d_in[5];
    const float* Wq    = (const float*)d_in[6];
    const float* Wk    = (const float*)d_in[7];
    const float* Wv    = (const float*)d_in[8];
    const float* Wo    = (const float*)d_in[9];
    const float* ffn_g = (const float*)d_in[10];
    const float* ffn_b = (const float*)d_in[11];
    const float* W1    = (const float*)d_in[12];
    const float* b1    = (const float*)d_in[13];
    const float* W2    = (const float*)d_in[14];
    const float* b2    = (const float*)d_in[15];
    const float* tn_g  = (const float*)d_in[16];
    const float* tn_b  = (const float*)d_in[17];
    const float* scale = (const float*)d_in[18];
    const float* Wd    = (const float*)d_in[19];
    const float* bd    = (const float*)d_in[20];
    const float* Wu    = (const float*)d_in[21];
    const float* bu    = (const float*)d_in[22];
    const float* books = (const float*)d_in[23];
    float* out = (float*)d_out;

    float* p_Qc  = sym<float>(g_Qc);
    float* p_K   = sym<float>(g_K);
    float* p_V   = sym<float>(g_V);
    float* p_y   = sym<float>(g_y);
    float* p_rD  = sym<float>(g_rD);
    float* p_zh  = sym<float>(g_zhat);
    float* p_qln = sym<float>(g_qln);
    float* p_q0  = sym<float>(g_q0);
    float* p_Q0  = sym<float>(g_Q0);
    float* p_y0  = sym<float>(g_y0);
    float* p_rD0 = sym<float>(g_rD0);

    u16* qlh = sym<u16>(u_qlnh); u16* qll = sym<u16>(u_qlnl);
    u16* kvh = sym<u16>(u_kvh);  u16* kvl = sym<u16>(u_kvl);
    u16* cth = sym<u16>(u_ctxh); u16* ctl = sym<u16>(u_ctxl);
    u16* lnh = sym<u16>(u_lnh);  u16* lnl = sym<u16>(u_lnl);
    u16* hh  = sym<u16>(u_hh);   u16* hl  = sym<u16>(u_hl);
    u16* xdh = sym<u16>(u_xdh);  u16* xdl = sym<u16>(u_xdl);
    u16* qdh = sym<u16>(u_qdh);  u16* qdl = sym<u16>(u_qdl);
    u16* q0h = sym<u16>(u_q0h);  u16* q0l = sym<u16>(u_q0l);
    u16* c0h = sym<u16>(u_ctx0h);u16* c0l = sym<u16>(u_ctx0l);
    u16* l0h = sym<u16>(u_ln0h); u16* l0l = sym<u16>(u_ln0l);
    u16* h0h = sym<u16>(u_h0h);  u16* h0l = sym<u16>(u_h0l);
    u16* x0h = sym<u16>(u_xd0h); u16* x0l = sym<u16>(u_xd0l);
    u16* d0h = sym<u16>(u_qd0h); u16* d0l = sym<u16>(u_qd0l);

    u16* wqh = sym<u16>(w_qh); u16* wql = sym<u16>(w_ql);
    u16* wkh = sym<u16>(w_kh); u16* wkl = sym<u16>(w_kl);
    u16* wvh = sym<u16>(w_vh); u16* wvl = sym<u16>(w_vl);
    u16* woh = sym<u16>(w_oh); u16* wol = sym<u16>(w_ol);
    u16* w1h = sym<u16>(w_1h); u16* w1l = sym<u16>(w_1l);
    u16* w2h = sym<u16>(w_2h); u16* w2l = sym<u16>(w_2l);
    u16* wdh = sym<u16>(w_dh); u16* wdl = sym<u16>(w_dl);
    u16* wuh = sym<u16>(w_uh); u16* wul = sym<u16>(w_ul);
    u16* bkh = sym<u16>(bk_h); u16* bkl = sym<u16>(bk_l);

    cudaFuncSetAttribute(rvq_k, cudaFuncAttributeMaxDynamicSharedMemorySize, RVQ_SMEM);

    // ---- prep ----
    prep_splits_k<<<11696, 256>>>(Wq, Wk, Wv, Wo, W1, W2, Wd, Wu, books, lnq_g, lnq_b);
    kvln2_k<<<M2, 256>>>(qa, lnkv_g, lnkv_b);

    // ---- pass A ----
    gemmb(kvh, kvl, wkh, wkl, p_K, nullptr, nullptr, nullptr, nullptr, MR, 512, 512, 0, 0,
          wvh, wvl, p_V,
          qlh, qll, wqh, wql, p_Qc, 16);
    attnA_k<<<M2, 256>>>(p_K, p_V);
    gemmb(cth, ctl, woh, wol, p_y, nullptr, nullptr, nullptr, p_qln, MR, 512, 512, 0, 2);
    ln_rows_k<<<MR, 256>>>(p_y, lnh, lnl, ffn_g, ffn_b);
    gemmb(lnh, lnl, w1h, w1l, nullptr, hh, hl, b1, nullptr, MR, 1024, 512, 1, 0);
    gemmb(hh, hl, w2h, w2l, p_y, nullptr, nullptr, b2, p_y, MR, 512, 1024, 0, 1);
    residA2_k<<<M2, 256>>>(zt, p_y, tn_g, tn_b, scale);
    gemmb(xdh, xdl, wdh, wdl, p_rD, nullptr, nullptr, bd, nullptr, MR, 96, 512, 0, 0);
    rvq_k<<<MR / 64, 256, RVQ_SMEM>>>(p_rD, qdh, qdl, books, bkh, bkl);
    gemmb(qdh, qdl, wuh, wul, p_zh, nullptr, nullptr, bu, p_y, MR, 512, 96, 0, 1);
    scatterA2_k<<<M2, 256>>>(p_zh, out);

    // ---- pass B ----
    q0ln_k<<<M2, 256>>>(lnq_g, lnq_b);
    gemmb4(q0h, q0l, wqh, wql, p_Q0, nullptr, nullptr, nullptr, nullptr, M2, 512, 512, 0, 0);
    attnB_k<<<M2, 256>>>(p_K, p_V);
    gemmb4(c0h, c0l, woh, wol, p_y0, nullptr, nullptr, nullptr, p_q0, M2, 512, 512, 0, 1);
    ln_rows_k<<<M2, 256>>>(p_y0, l0h, l0l, ffn_g, ffn_b);
    gemmb4(l0h, l0l, w1h, w1l, nullptr, h0h, h0l, b1, nullptr, M2, 1024, 512, 1, 0);
    gemmb4(h0h, h0l, w2h, w2l, p_y0, nullptr, nullptr, b2, p_y0, M2, 512, 1024, 0, 1);
    residB_k<<<M2, 256>>>(zt, p_y0, tn_g, tn_b, scale);
    gemmb4(x0h, x0l, wdh, wdl, p_rD0, nullptr, nullptr, bd, nullptr, M2, 96, 512, 0, 0);
    rvq_k<<<M2 / 64, 256, RVQ_SMEM>>>(p_rD0, d0h, d0l, books, bkh, bkl);
    gemmb4(d0h, d0l, wuh, wul, out, nullptr, nullptr, bu, p_y0, M2, 512, 96, 0, 1, 2);
}

// round 17
// speedup vs baseline: 1.5006x; 1.5006x over previous
#include <cuda_runtime.h>
#include <cuda_bf16.h>
#include <math.h>
#include <stdint.h>

typedef unsigned short u16;

// ---------------- problem constants ----------------
#define Bb    8
#define Cc    512
#define Tt    4096
#define CHK   16
#define CD    96
#define NBOOK 8
#define NEMB  1024
#define NCH   256
#define MR    (NCH*Bb*CHK)   // 32768
#define M2    (NCH*Bb)       // 2048

// ---------------- fp32 scratch ----------------
__device__ float g_pe[Cc*CHK];
__device__ float g_qln[CHK*Cc];
__device__ float g_Qc[CHK*Cc];
__device__ float g_cnorm[NBOOK*NEMB];
__device__ float g_K   [(size_t)MR*Cc];
__device__ float g_V   [(size_t)MR*Cc];
__device__ float g_y   [(size_t)MR*Cc];
__device__ float g_rD  [(size_t)MR*CD];
__device__ float g_zhat[(size_t)MR*Cc];
__device__ float g_prev[(size_t)M2*Cc];
__device__ float g_q0  [(size_t)M2*Cc];
__device__ float g_Q0  [(size_t)M2*Cc];
__device__ float g_y0  [(size_t)M2*Cc];
__device__ float g_rD0 [(size_t)M2*CD];
__device__ float g_zh0 [(size_t)M2*Cc];

// ---------------- bf16 hi/lo scratch (activations) ----------------
__device__ __align__(16) u16 u_qlnh[CHK*Cc],  u_qlnl[CHK*Cc];
__device__ __align__(16) u16 u_kvh [(size_t)MR*Cc],  u_kvl [(size_t)MR*Cc];
__device__ __align__(16) u16 u_ctxh[(size_t)MR*Cc],  u_ctxl[(size_t)MR*Cc];
__device__ __align__(16) u16 u_lnh [(size_t)MR*Cc],  u_lnl [(size_t)MR*Cc];
__device__ __align__(16) u16 u_hh  [(size_t)MR*2*Cc],u_hl  [(size_t)MR*2*Cc];
__device__ __align__(16) u16 u_xdh [(size_t)MR*Cc],  u_xdl [(size_t)MR*Cc];
__device__ __align__(16) u16 u_qdh [(size_t)MR*CD],  u_qdl [(size_t)MR*CD];
__device__ __align__(16) u16 u_q0h [(size_t)M2*Cc],  u_q0l [(size_t)M2*Cc];
__device__ __align__(16) u16 u_ctx0h[(size_t)M2*Cc], u_ctx0l[(size_t)M2*Cc];
__device__ __align__(16) u16 u_ln0h[(size_t)M2*Cc],  u_ln0l[(size_t)M2*Cc];
__device__ __align__(16) u16 u_h0h [(size_t)M2*2*Cc],u_h0l [(size_t)M2*2*Cc];
__device__ __align__(16) u16 u_xd0h[(size_t)M2*Cc],  u_xd0l[(size_t)M2*Cc];
__device__ __align__(16) u16 u_qd0h[(size_t)M2*CD],  u_qd0l[(size_t)M2*CD];

// ---------------- bf16 hi/lo weights (all stored [N][K]) ----------------
__device__ __align__(16) u16 w_qh[Cc*Cc],  w_ql[Cc*Cc];
__device__ __align__(16) u16 w_kh[Cc*Cc],  w_kl[Cc*Cc];
__device__ __align__(16) u16 w_vh[Cc*Cc],  w_vl[Cc*Cc];
__device__ __align__(16) u16 w_oh[Cc*Cc],  w_ol[Cc*Cc];
__device__ __align__(16) u16 w_1h[2*Cc*Cc],w_1l[2*Cc*Cc];
__device__ __align__(16) u16 w_2h[2*Cc*Cc],w_2l[2*Cc*Cc];
__device__ __align__(16) u16 w_dh[CD*Cc],  w_dl[CD*Cc];
__device__ __align__(16) u16 w_uh[Cc*CD],  w_ul[Cc*CD];
__device__ __align__(16) u16 bk_h[NBOOK*NEMB*CD], bk_l[NBOOK*NEMB*CD];

// ---------------- helpers ----------------
__device__ __forceinline__ float geluf(float x) {
    return 0.5f * x * (1.0f + erff(x * 0.70710678118654752440f));
}
__device__ __forceinline__ void split1(float v, u16& h, u16& l) {
    __nv_bfloat16 hb = __float2bfloat16(v);
    __nv_bfloat16 lb = __float2bfloat16(v - __bfloat162float(hb));
    h = __bfloat16_as_ushort(hb);
    l = __bfloat16_as_ushort(lb);
}
__device__ __forceinline__ void split2(float v0, float v1, uint32_t& hi, uint32_t& lo) {
    u16 h0, l0, h1, l1;
    split1(v0, h0, l0); split1(v1, h1, l1);
    hi = (uint32_t)h0 | ((uint32_t)h1 << 16);
    lo = (uint32_t)l0 | ((uint32_t)l1 << 16);
}
__device__ __forceinline__ uint32_t smem_u32(const void* p) {
    uint32_t a;
    asm("{ .reg .u64 t; cvta.to.shared.u64 t, %1; cvt.u32.u64 %0, t; }" : "=r"(a) : "l"(p));
    return a;
}
__device__ __forceinline__ void cpa16(uint32_t dst, const void* src, int sz) {
    asm volatile("cp.async.cg.shared.global [%0], [%1], 16, %2;"
                 :: "r"(dst), "l"(src), "r"(sz) : "memory");
}
__device__ __forceinline__ void mma_bf16(float* c, const uint32_t* a, const uint32_t* b) {
    asm volatile(
        "mma.sync.aligned.m16n8k16.row.col.f32.bf16.bf16.f32 "
        "{%0,%1,%2,%3}, {%4,%5,%6,%7}, {%8,%9}, {%0,%1,%2,%3};"
        : "+f"(c[0]), "+f"(c[1]), "+f"(c[2]), "+f"(c[3])
        : "r"(a[0]), "r"(a[1]), "r"(a[2]), "r"(a[3]), "r"(b[0]), "r"(b[1]));
}
__device__ __forceinline__ void ldsm4(uint32_t& r0, uint32_t& r1, uint32_t& r2,
                                      uint32_t& r3, uint32_t addr) {
    asm volatile("ldmatrix.sync.aligned.m8n8.x4.shared.b16 {%0,%1,%2,%3}, [%4];"
                 : "=r"(r0), "=r"(r1), "=r"(r2), "=r"(r3) : "r"(addr));
}

// ---------------- LN helper ----------------
__device__ __forceinline__ float2 block_ln2(float x0, float x1, int c0, int c1,
                                            const float* __restrict__ g,
                                            const float* __restrict__ b,
                                            float* red)
{
    int tid = threadIdx.x, lane = tid & 31, w = tid >> 5;
    float s = x0 + x1;
#pragma unroll
    for (int o = 16; o; o >>= 1) s += __shfl_xor_sync(0xffffffffu, s, o);
    if (lane == 0) red[w] = s;
    __syncthreads();
    float tot = 0.f;
#pragma unroll
    for (int i = 0; i < 8; i++) tot += red[i];
    float mean = tot * (1.0f / 512.0f);
    float d0 = x0 - mean, d1 = x1 - mean;
    float q = d0 * d0 + d1 * d1;
#pragma unroll
    for (int o = 16; o; o >>= 1) q += __shfl_xor_sync(0xffffffffu, q, o);
    __syncthreads();
    if (lane == 0) red[w] = q;
    __syncthreads();
    float tot2 = 0.f;
#pragma unroll
    for (int i = 0; i < 8; i++) tot2 += red[i];
    float inv = rsqrtf(tot2 * (1.0f / 512.0f) + 1e-5f);
    return make_float2(d0 * inv * g[c0] + b[c0], d1 * inv * g[c1] + b[c1]);
}

// ---------------- merged prep: splits + cnorm + pe/qln, ONE launch ----------
__global__ void prep_splits_k(const float* __restrict__ Wq, const float* __restrict__ Wk,
                              const float* __restrict__ Wv, const float* __restrict__ Wo,
                              const float* __restrict__ W1, const float* __restrict__ W2,
                              const float* __restrict__ Wd, const float* __restrict__ Wu,
                              const float* __restrict__ books,
                              const float* __restrict__ lnq_g,
                              const float* __restrict__ lnq_b)
{
    __shared__ float red[8];
    int b = blockIdx.x, tid = threadIdx.x;
    u16 h, l;
    if (b < 4096) {
        int e = b * 256 + tid;
        int w = e >> 18, idx = e & 262143;
        const float* W = (w == 0) ? Wq : (w == 1) ? Wk : (w == 2) ? Wv : Wo;
        u16* oh = (w == 0) ? w_qh : (w == 1) ? w_kh : (w == 2) ? w_vh : w_oh;
        u16* ol = (w == 0) ? w_ql : (w == 1) ? w_kl : (w == 2) ? w_vl : w_ol;
        int k = idx >> 9, n = idx & 511;
        split1(W[idx], h, l);
        oh[(size_t)n * 512 + k] = h;
        ol[(size_t)n * 512 + k] = l;
    } else if (b < 6144) {
        int e = (b - 4096) * 256 + tid;
        int k = e >> 10, n = e & 1023;
        split1(W1[e], h, l);
        w_1h[(size_t)n * 512 + k] = h;
        w_1l[(size_t)n * 512 + k] = l;
    } else if (b < 8192) {
        int e = (b - 6144) * 256 + tid;
        int k = e >> 9, n = e & 511;
        split1(W2[e], h, l);
        w_2h[(size_t)n * 1024 + k] = h;
        w_2l[(size_t)n * 1024 + k] = l;
    } else if (b < 8384) {
        int e = (b - 8192) * 256 + tid;
        split1(Wd[e], h, l); w_dh[e] = h; w_dl[e] = l;
    } else if (b < 8576) {
        int e = (b - 8384) * 256 + tid;
        split1(Wu[e], h, l); w_uh[e] = h; w_ul[e] = l;
    } else if (b < 11648) {
        int e = (b - 8576) * 256 + tid;
        split1(books[e], h, l); bk_h[e] = h; bk_l[e] = l;
    } else if (b < 11680) {
        int idx = (b - 11648) * 256 + tid;
        const float* e = books + (size_t)idx * CD;
        float s = 0.f;
#pragma unroll
        for (int d = 0; d < CD; d++) { float v = e[d]; s += v * v; }
        g_cnorm[idx] = 0.5f * s;
    } else {
        int t = b - 11680;
        int c0 = 2 * tid, c1 = c0 + 1;
        double dv = exp((double)c0 * (-log(10000.0) / 512.0));
        double ang = (double)t * dv;
        float v0 = (float)sin(ang);
        float v1 = (float)cos(ang);
        g_pe[c0 * CHK + t] = v0;
        g_pe[c1 * CHK + t] = v1;
        float2 y = block_ln2(v0, v1, c0, c1, lnq_g, lnq_b, red);
        g_qln[t * Cc + c0] = y.x;
        g_qln[t * Cc + c1] = y.y;
        split1(y.x, h, l); u_qlnh[t * Cc + c0] = h; u_qlnl[t * Cc + c0] = l;
        split1(y.y, h, l); u_qlnh[t * Cc + c1] = h; u_qlnl[t * Cc + c1] = l;
    }
}

// ---------------- prep kernels ----------------
__global__ void __launch_bounds__(256) kvln2_k(const float* __restrict__ qa,
                                               const float* __restrict__ g,
                                               const float* __restrict__ b)
{
    __shared__ float tile[16][513];
    int blk = blockIdx.x, tid = threadIdx.x;
    int s = blk >> 3, bb = blk & 7;
#pragma unroll
    for (int l = 0; l < 8; l++) {
        int e = tid + l * 256;
        int c = e >> 2, seg = e & 3;
        float4 v = *(const float4*)(qa + ((size_t)(bb * Cc + c)) * Tt + s * CHK + seg * 4);
        tile[seg * 4 + 0][c] = v.x;
        tile[seg * 4 + 1][c] = v.y;
        tile[seg * 4 + 2][c] = v.z;
        tile[seg * 4 + 3][c] = v.w;
    }
    __syncthreads();
    int w = tid >> 5, lane = tid & 31;
#pragma unroll
    for (int t = w; t < 16; t += 8) {
        int n = s * 128 + bb * 16 + t;
        float xs[16], sum = 0.f;
#pragma unroll
        for (int k = 0; k < 16; k++) {
            int c = lane + 32 * k;
            float x = tile[t][c] + g_pe[c * CHK + t];
            xs[k] = x; sum += x;
        }
#pragma unroll
        for (int o = 16; o; o >>= 1) sum += __shfl_xor_sync(0xffffffffu, sum, o);
        float mean = sum * (1.0f / 512.0f);
        float q = 0.f;
#pragma unroll
        for (int k = 0; k < 16; k++) { float d = xs[k] - mean; q += d * d; }
#pragma unroll
        for (int o = 16; o; o >>= 1) q += __shfl_xor_sync(0xffffffffu, q, o);
        float inv = rsqrtf(q * (1.0f / 512.0f) + 1e-5f);
#pragma unroll
        for (int k = 0; k < 16; k++) {
            int c = lane + 32 * k;
            float o2 = (xs[k] - mean) * inv * g[c] + b[c];
            u16 h, l2; split1(o2, h, l2);
            u_kvh[(size_t)n * Cc + c] = h;
            u_kvl[(size_t)n * Cc + c] = l2;
        }
    }
}

__global__ void ln_rows_k(const float* __restrict__ in, u16* __restrict__ oh,
                          u16* __restrict__ ol,
                          const float* __restrict__ g, const float* __restrict__ b)
{
    __shared__ float red[8];
    int n = blockIdx.x, tid = threadIdx.x;
    int c0 = tid, c1 = tid + 256;
    float x0 = in[(size_t)n * Cc + c0];
    float x1 = in[(size_t)n * Cc + c1];
    float2 y = block_ln2(x0, x1, c0, c1, g, b, red);
    u16 h, l;
    split1(y.x, h, l); oh[(size_t)n * Cc + c0] = h; ol[(size_t)n * Cc + c0] = l;
    split1(y.y, h, l); oh[(size_t)n * Cc + c1] = h; ol[(size_t)n * Cc + c1] = l;
}

__global__ void __launch_bounds__(256) residA2_k(const float* __restrict__ zt,
                                                 const float* __restrict__ y,
                                                 const float* __restrict__ g,
                                                 const float* __restrict__ b,
                                                 const float* __restrict__ scale)
{
    __shared__ float tile[16][513];
    int blk = blockIdx.x, tid = threadIdx.x;
    int s = blk >> 3, bb = blk & 7;
    float sc = fminf(fmaxf(scale[0], 0.005f), 0.5f);
#pragma unroll
    for (int l = 0; l < 8; l++) {
        int e = tid + l * 256;
        int c = e >> 2, seg = e & 3;
        float4 v = *(const float4*)(zt + ((size_t)(bb * Cc + c)) * Tt + s * CHK + seg * 4);
        tile[seg * 4 + 0][c] = v.x;
        tile[seg * 4 + 1][c] = v.y;
        tile[seg * 4 + 2][c] = v.z;
        tile[seg * 4 + 3][c] = v.w;
    }
    __syncthreads();
    int w = tid >> 5, lane = tid & 31;
#pragma unroll
    for (int t = w; t < 16; t += 8) {
        int n = s * 128 + bb * 16 + t;
        float xs[16], sum = 0.f;
#pragma unroll
        for (int k = 0; k < 16; k++) {
            int c = lane + 32 * k;
            float x = tile[t][c] - y[(size_t)n * Cc + c];
            xs[k] = x; sum += x;
        }
#pragma unroll
        for (int o = 16; o; o >>= 1) sum += __shfl_xor_sync(0xffffffffu, sum, o);
        float mean = sum * (1.0f / 512.0f);
        float q = 0.f;
#pragma unroll
        for (int k = 0; k < 16; k++) { float d = xs[k] - mean; q += d * d; }
#pragma unroll
        for (int o = 16; o; o >>= 1) q += __shfl_xor_sync(0xffffffffu, q, o);
        float inv = rsqrtf(q * (1.0f / 512.0f) + 1e-5f);
#pragma unroll
        for (int k = 0; k < 16; k++) {
            int c = lane + 32 * k;
            float o2 = sc * tanhf((xs[k] - mean) * inv * g[c] + b[c]);
            u16 h, l2; split1(o2, h, l2);
            u_xdh[(size_t)n * Cc + c] = h;
            u_xdl[(size_t)n * Cc + c] = l2;
        }
    }
}

__global__ void residB_k(const float* __restrict__ zt, const float* __restrict__ y,
                         const float* __restrict__ g, const float* __restrict__ b,
                         const float* __restrict__ scale)
{
    __shared__ float red[8];
    int n = blockIdx.x, tid = threadIdx.x;
    int s = n >> 3, bb = n & 7;
    int tg = s * CHK;
    float sc = fminf(fmaxf(scale[0], 0.005f), 0.5f);
    int c0 = tid, c1 = tid + 256;
    float x0 = zt[((size_t)(bb * Cc + c0)) * Tt + tg] - y[(size_t)n * Cc + c0];
    float x1 = zt[((size_t)(bb * Cc + c1)) * Tt + tg] - y[(size_t)n * Cc + c1];
    float2 o = block_ln2(x0, x1, c0, c1, g, b, red);
    u16 h, l;
    split1(sc * tanhf(o.x), h, l); u_xd0h[(size_t)n * Cc + c0] = h; u_xd0l[(size_t)n * Cc + c0] = l;
    split1(sc * tanhf(o.y), h, l); u_xd0h[(size_t)n * Cc + c1] = h; u_xd0l[(size_t)n * Cc + c1] = l;
}

__global__ void q0ln_k(const float* __restrict__ g, const float* __restrict__ b)
{
    __shared__ float red[8];
    int n = blockIdx.x, tid = threadIdx.x;
    int s = n >> 3;
    int c0 = tid, c1 = tid + 256;
    float p0 = (s > 0) ? g_prev[(size_t)(n - Bb) * Cc + c0] : 0.f;
    float p1 = (s > 0) ? g_prev[(size_t)(n - Bb) * Cc + c1] : 0.f;
    float x0 = p0 + g_pe[c0 * CHK + 0];
    float x1 = p1 + g_pe[c1 * CHK + 0];
    float2 y = block_ln2(x0, x1, c0, c1, g, b, red);
    g_q0[(size_t)n * Cc + c0] = y.x;
    g_q0[(size_t)n * Cc + c1] = y.y;
    u16 h, l;
    split1(y.x, h, l); u_q0h[(size_t)n * Cc + c0] = h; u_q0l[(size_t)n * Cc + c0] = l;
    split1(y.y, h, l); u_q0h[(size_t)n * Cc + c1] = h; u_q0l[(size_t)n * Cc + c1] = l;
}

__global__ void __launch_bounds__(256) scatterA2_k(const float* __restrict__ zhat,
                                                   float* __restrict__ out)
{
    __shared__ float tile[16][513];
    int blk = blockIdx.x, tid = threadIdx.x;
    int s = blk >> 3, bb = blk & 7;
    int n0 = s * 128 + bb * 16;
#pragma unroll
    for (int l = 0; l < 32; l++) {
        int e = tid + l * 256;
        int t = e >> 9, c = e & 511;
        float v = zhat[((size_t)(n0 + t)) * Cc + c];
        tile[t][c] = v;
        if (t == 15) g_prev[(size_t)(s * 8 + bb) * Cc + c] = v;
    }
    __syncthreads();
#pragma unroll
    for (int l = 0; l < 8; l++) {
        int e = tid + l * 256;
        int c = e >> 2, seg = e & 3;
        float4 v = make_float4(tile[seg * 4 + 0][c], tile[seg * 4 + 1][c],
                               tile[seg * 4 + 2][c], tile[seg * 4 + 3][c]);
        *(float4*)(out + ((size_t)(bb * Cc + c)) * Tt + s * CHK + seg * 4) = v;
    }
}

// ---------------- split-bf16 GEMM ----------------
__device__ __forceinline__ void gb_stage(uint32_t sbase,
    const u16* __restrict__ Ah, const u16* __restrict__ Al,
    const u16* __restrict__ Bh, const u16* __restrict__ Bl,
    int m0, int n0, int M, int N, int K, int k0, int tid)
{
#pragma unroll
    for (int l = 0; l < 2; l++) {
        int e = tid + l * 256;
        int row = e >> 2, seg = e & 3;
        uint32_t d = sbase + row * 80 + seg * 16;
        size_t oa = (size_t)(m0 + row) * K + k0 + seg * 8;
        int szA = (m0 + row < M) ? 16 : 0;
        cpa16(d,         Ah + oa, szA);
        cpa16(d + 10240, Al + oa, szA);
        size_t ob = (size_t)(n0 + row) * K + k0 + seg * 8;
        int szB = (n0 + row < N) ? 16 : 0;
        cpa16(d + 20480, Bh + ob, szB);
        cpa16(d + 30720, Bl + ob, szB);
    }
    asm volatile("cp.async.commit_group;" ::: "memory");
}

template<int NS>
__global__ void __launch_bounds__(256) gemm_b_k(
    const u16* __restrict__ Ah, const u16* __restrict__ Al,
    const u16* __restrict__ Bh, const u16* __restrict__ Bl,
    float* __restrict__ Cm, u16* __restrict__ Chi, u16* __restrict__ Clo,
    const float* __restrict__ bias, const float* __restrict__ resid,
    int M, int N, int K, int act, int rmode,
    const u16* __restrict__ Bh2, const u16* __restrict__ Bl2,
    float* __restrict__ Cm2,
    const u16* __restrict__ Ah3, const u16* __restrict__ Al3,
    const u16* __restrict__ Bh3, const u16* __restrict__ Bl3,
    float* __restrict__ Cm3, int M3, int omode)
{
    extern __shared__ char smem[];
    uint32_t sb = smem_u32(smem);
    int tid = threadIdx.x, wid = tid >> 5, lane = tid & 31;
    int g = lane >> 2, tg = lane & 3;
    int wm = (wid >> 2) * 64, wn = (wid & 3) * 32;
    int m0 = blockIdx.y * 128, n0 = blockIdx.x * 128;

    const u16 *Ahp = Ah, *Alp = Al, *Bhp = Bh, *Blp = Bl;
    float* Cmp = Cm;
    if (blockIdx.z == 1) { Bhp = Bh2; Blp = Bl2; Cmp = Cm2; }
    else if (blockIdx.z == 2) {
        Ahp = Ah3; Alp = Al3; Bhp = Bh3; Blp = Bl3; Cmp = Cm3; M = M3;
        if (m0 >= M) return;
    }

    float acc[4][4][4];
#pragma unroll
    for (int i = 0; i < 4; i++)
#pragma unroll
        for (int j = 0; j < 4; j++)
#pragma unroll
            for (int r = 0; r < 4; r++) acc[i][j][r] = 0.f;

    uint32_t aOffH = (uint32_t)(wm + (lane & 15)) * 80 + ((lane >> 4) & 1) * 16;
    uint32_t aOffL = aOffH + 10240;
    uint32_t bOffH = 20480u + (uint32_t)(wn + ((lane >> 4) & 1) * 8 + (lane & 7)) * 80
                   + ((lane >> 3) & 1) * 16;
    uint32_t bOffL = bOffH + 10240;

    int nch = K >> 5;
#pragma unroll
    for (int s = 0; s < NS - 1; s++) {
        if (s < nch)
            gb_stage(sb + s * 40960, Ahp, Alp, Bhp, Blp, m0, n0, M, N, K, s * 32, tid);
        else
            asm volatile("cp.async.commit_group;" ::: "memory");
    }

    for (int c = 0; c < nch; c++) {
        if (NS == 2) asm volatile("cp.async.wait_group 0;" ::: "memory");
        else         asm volatile("cp.async.wait_group 2;" ::: "memory");
        __syncthreads();
        int nx = c + NS - 1;
        if (nx < nch)
            gb_stage(sb + (nx & (NS - 1)) * 40960, Ahp, Alp, Bhp, Blp,
                     m0, n0, M, N, K, nx * 32, tid);
        else
            asm volatile("cp.async.commit_group;" ::: "memory");

        uint32_t sbuf = sb + (c & (NS - 1)) * 40960;
#pragma unroll
        for (int ks = 0; ks < 2; ks++) {
            uint32_t kb = ks * 32;
            uint32_t bh[4][2], bl[4][2];
#pragma unroll
            for (int nfp = 0; nfp < 2; nfp++) {
                ldsm4(bh[2*nfp][0], bh[2*nfp][1], bh[2*nfp+1][0], bh[2*nfp+1][1],
                      sbuf + bOffH + nfp * 1280 + kb);
                ldsm4(bl[2*nfp][0], bl[2*nfp][1], bl[2*nfp+1][0], bl[2*nfp+1][1],
                      sbuf + bOffL + nfp * 1280 + kb);
            }
#pragma unroll
            for (int mf = 0; mf < 4; mf++) {
                uint32_t ah[4], al[4];
                ldsm4(ah[0], ah[1], ah[2], ah[3], sbuf + aOffH + mf * 1280 + kb);
                ldsm4(al[0], al[1], al[2], al[3], sbuf + aOffL + mf * 1280 + kb);
#pragma unroll
                for (int nf = 0; nf < 4; nf++) {
                    mma_bf16(acc[mf][nf], ah, bl[nf]);
                    mma_bf16(acc[mf][nf], al, bh[nf]);
                    mma_bf16(acc[mf][nf], ah, bh[nf]);
                }
            }
        }
    }

#pragma unroll
    for (int mf = 0; mf < 4; mf++) {
        int mA = m0 + wm + mf * 16 + g;
#pragma unroll
        for (int nf = 0; nf < 4; nf++) {
            int nc = n0 + wn + nf * 8 + 2 * tg;
#pragma unroll
            for (int half = 0; half < 2; half++) {
                int m = mA + half * 8;
                if (m >= M) continue;
#pragma unroll
                for (int jj = 0; jj < 2; jj++) {
                    int nn = nc + jj;
                    if (nn >= N) continue;
                    float v = acc[mf][nf][half * 2 + jj];
                    if (bias)  v += bias[nn];
                    if (rmode == 1) v += resid[(size_t)m * N + nn];
                    else if (rmode == 2) v += resid[(size_t)(m & 15) * 512 + nn];
                    if (act == 1) v = geluf(v);
                    if (Chi) {
                        u16 h, l; split1(v, h, l);
                        Chi[(size_t)m * N + nn] = h;
                        Clo[(size_t)m * N + nn] = l;
                    } else if (omode == 2) {
                        Cmp[((size_t)((m & 7) * Cc + nn)) * Tt + (m >> 3) * CHK] = v;
                    } else {
                        Cmp[(size_t)m * N + nn] = v;
                    }
                }
            }
        }
    }
}

// ---------------- attention (514 stride, float2-vectorized: conflict-free) --
__global__ void __launch_bounds__(256) attnA_k(const float* __restrict__ Kmat,
                                               const float* __restrict__ Vmat)
{
    __shared__ float sKV[16][514];   // 514: stride mod 32 = 2 -> K-rows conflict-free
    __shared__ float sS[16 * 8 * 16];
    int blk = blockIdx.x, tid = threadIdx.x;
    size_t n0 = (size_t)blk * CHK;

    // K fill (float2; row starts 8B-aligned)
#pragma unroll
    for (int l = 0; l < 16; l++) {
        int e = tid + l * 256;             // 0..4095 = row*256 + c2
        int row = e >> 8, c2 = (e & 255) << 1;
        float2 v = *(const float2*)(Kmat + (n0 + row) * Cc + c2);
        *(float2*)&sKV[row][c2] = v;
    }
    __syncthreads();
    { // scores: thread = (t,k); float2 loads, scalar-order accumulation
        int t = tid >> 4, k = tid & 15;
        const float2* qrow = (const float2*)(g_Qc + t * Cc);
#pragma unroll
        for (int h = 0; h < 8; h++) {
            float s = 0.f;
            const float2* kp = (const float2*)&sKV[k][h * 64];
            const float2* qp = qrow + h * 32;
#pragma unroll
            for (int d2 = 0; d2 < 32; d2++) {
                float2 q = qp[d2], kk = kp[d2];
                s = fmaf(q.x, kk.x, s);
                s = fmaf(q.y, kk.y, s);
            }
            sS[(t * 8 + h) * 16 + k] = s * 0.125f;
        }
    }
    __syncthreads();
    if (tid < 128) {
        float* p = &sS[tid * 16];
        float m = p[0];
#pragma unroll
        for (int k = 1; k < 16; k++) m = fmaxf(m, p[k]);
        float sum = 0.f;
#pragma unroll
        for (int k = 0; k < 16; k++) { float e = expf(p[k] - m); p[k] = e; sum += e; }
        float inv = 1.0f / sum;
#pragma unroll
        for (int k = 0; k < 16; k++) p[k] *= inv;
    }
    __syncthreads();
    // V fill (float2)
#pragma unroll
    for (int l = 0; l < 16; l++) {
        int e = tid + l * 256;
        int row = e >> 8, c2 = (e & 255) << 1;
        float2 v = *(const float2*)(Vmat + (n0 + row) * Cc + c2);
        *(float2*)&sKV[row][c2] = v;
    }
    __syncthreads();
#pragma unroll
    for (int cc = 0; cc < 2; cc++) {
        int c = tid + cc * 256;
        int h = c >> 6;
#pragma unroll
        for (int t = 0; t < 16; t++) {
            float a = 0.f;
            const float* at = &sS[(t * 8 + h) * 16];
#pragma unroll
            for (int k = 0; k < 16; k++) a = fmaf(at[k], sKV[k][c], a);
            u16 hh, ll; split1(a, hh, ll);
            u_ctxh[(n0 + t) * Cc + c] = hh;
            u_ctxl[(n0 + t) * Cc + c] = ll;
        }
    }
}

__global__ void __launch_bounds__(256) attnB_k(const float* __restrict__ Kmat,
                                               const float* __restrict__ Vmat)
{
    __shared__ float sKV[16][514];
    __shared__ float sS[8 * 16];
    int blk = blockIdx.x, tid = threadIdx.x;
    size_t n0 = (size_t)blk * CHK;

#pragma unroll
    for (int l = 0; l < 16; l++) {
        int e = tid + l * 256;
        int row = e >> 8, c2 = (e & 255) << 1;
        float2 v = *(const float2*)(Kmat + (n0 + row) * Cc + c2);
        *(float2*)&sKV[row][c2] = v;
    }
    __syncthreads();
    if (tid < 128) {
        int h = tid >> 4, k = tid & 15;
        const float2* qp = (const float2*)(g_Q0 + (size_t)blk * Cc + h * 64);
        const float2* kp = (const float2*)&sKV[k][h * 64];
        float s = 0.f;
#pragma unroll
        for (int d2 = 0; d2 < 32; d2++) {
            float2 q = qp[d2], kk = kp[d2];
            s = fmaf(q.x, kk.x, s);
            s = fmaf(q.y, kk.y, s);
        }
        sS[h * 16 + k] = s * 0.125f;
    }
    __syncthreads();
    if (tid < 8) {
        float* p = &sS[tid * 16];
        float m = p[0];
#pragma unroll
        for (int k = 1; k < 16; k++) m = fmaxf(m, p[k]);
        float sum = 0.f;
#pragma unroll
        for (int k = 0; k < 16; k++) { float e = expf(p[k] - m); p[k] = e; sum += e; }
        float inv = 1.0f / sum;
#pragma unroll
        for (int k = 0; k < 16; k++) p[k] *= inv;
    }
    __syncthreads();
#pragma unroll
    for (int l = 0; l < 16; l++) {
        int e = tid + l * 256;
        int row = e >> 8, c2 = (e & 255) << 1;
        float2 v = *(const float2*)(Vmat + (n0 + row) * Cc + c2);
        *(float2*)&sKV[row][c2] = v;
    }
    __syncthreads();
#pragma unroll
    for (int cc = 0; cc < 2; cc++) {
        int c = tid + cc * 256;
        int h = c >> 6;
        float a = 0.f;
        const float* at = &sS[h * 16];
#pragma unroll
        for (int k = 0; k < 16; k++) a = fmaf(at[k], sKV[k][c], a);
        u16 hh, ll; split1(a, hh, ll);
        u_ctx0h[(size_t)blk * Cc + c] = hh;
        u_ctx0l[(size_t)blk * Cc + c] = ll;
    }
}

// ---------------- residual VQ ----------------
#define RVQ_SMEM 109568

__device__ __forceinline__ void rvq_prefetch(uint32_t sb, uint32_t dBh, uint32_t dBl,
    const u16* __restrict__ bkh, const u16* __restrict__ bkl,
    float* sHNbuf, int k, int ct, int tid)
{
    const u16* srcH = bkh + ((size_t)k * NEMB + ct * 64) * CD;
    const u16* srcL = bkl + ((size_t)k * NEMB + ct * 64) * CD;
#pragma unroll
    for (int l = 0; l < 3; l++) {
        int e = tid + l * 256;
        int c = e / 12, s2 = e - c * 12;
        cpa16(sb + dBh + c * 208 + s2 * 16, srcH + c * 96 + s2 * 8, 16);
        cpa16(sb + dBl + c * 208 + s2 * 16, srcL + c * 96 + s2 * 8, 16);
    }
    asm volatile("cp.async.commit_group;" ::: "memory");
    if (tid < 64) sHNbuf[tid] = g_cnorm[k * NEMB + ct * 64 + tid];
}

__global__ void __launch_bounds__(256) rvq_k(const float* __restrict__ rD,
                                             u16* __restrict__ qh, u16* __restrict__ ql,
                                             const float* __restrict__ books,
                                             const u16* __restrict__ bkh,
                                             const u16* __restrict__ bkl)
{
    extern __shared__ char sm[];
    float* sRes  = (float*)sm;
    uint32_t sb  = smem_u32(sm);
    const uint32_t oAh = 24832, oAl = 38144;
    const uint32_t oBhArr[2] = { 51456, 78080 };
    const uint32_t oBlArr[2] = { 64768, 91392 };
    float* sHN    = (float*)(sm + 104704);
    float* sScore = (float*)(sm + 105216);
    int*   sIdx   = (int*)  (sm + 107264);
    int*   sBest  = (int*)  (sm + 109312);

    int tid = threadIdx.x, wid = tid >> 5, lane = tid & 31;
    int g = lane >> 2, tg = lane & 3;
    int m0 = blockIdx.x * 64;

    for (int e = tid; e < 64 * 96; e += 256) {
        int r = e / 96, d = e - r * 96;
        sRes[r * 97 + d] = rD[(size_t)(m0 + r) * CD + d];
    }

    uint32_t aoff = (uint32_t)(lane & 15) * 208 + ((lane >> 4) & 1) * 16;
    uint32_t boff = (uint32_t)(wid * 8 + (lane & 7)) * 208 + ((lane >> 3) & 3) * 16;

    for (int k = 0; k < NBOOK; k++) {
        __syncthreads();
        rvq_prefetch(sb, oBhArr[0], oBlArr[0], bkh, bkl, sHN + 0, k, 0, tid);
        for (int e = tid; e < 64 * 48; e += 256) {
            int r = e / 48, w = e - r * 48;
            float v0 = sRes[r * 97 + 2 * w], v1 = sRes[r * 97 + 2 * w + 1];
            uint32_t hi, lo; split2(v0, v1, hi, lo);
            *(uint32_t*)(sm + oAh + r * 208 + w * 4) = hi;
            *(uint32_t*)(sm + oAl + r * 208 + w * 4) = lo;
        }
        float best[8]; int bidx[8];
#pragma unroll
        for (int s = 0; s < 8; s++) { best[s] = -3.0e38f; bidx[s] = 0x7fffffff; }

        for (int ct = 0; ct < 16; ct++) {
            int buf = ct & 1;
            if (ct + 1 < 16) {
                rvq_prefetch(sb, oBhArr[buf ^ 1], oBlArr[buf ^ 1], bkh, bkl,
                             sHN + 64 * (buf ^ 1), k, ct + 1, tid);
                asm volatile("cp.async.wait_group 1;" ::: "memory");
            } else {
                asm volatile("cp.async.wait_group 0;" ::: "memory");
            }
            __syncthreads();

            const uint32_t oBh = oBhArr[buf], oBl = oBlArr[buf];
            const float* sHNb = sHN + 64 * buf;

            float acc[4][4];
#pragma unroll
            for (int i = 0; i < 4; i++)
#pragma unroll
                for (int j = 0; j < 4; j++) acc[i][j] = 0.f;

#pragma unroll
            for (int kcp = 0; kcp < 3; kcp++) {
                uint32_t bhv[4], blv[4];
                ldsm4(bhv[0], bhv[1], bhv[2], bhv[3], sb + oBh + boff + kcp * 64);
                ldsm4(blv[0], blv[1], blv[2], blv[3], sb + oBl + boff + kcp * 64);
#pragma unroll
                for (int sub = 0; sub < 2; sub++) {
                    uint32_t bh2[2] = { bhv[sub * 2], bhv[sub * 2 + 1] };
                    uint32_t bl2[2] = { blv[sub * 2], blv[sub * 2 + 1] };
                    uint32_t ka = (uint32_t)(kcp * 2 + sub) * 32;
#pragma unroll
                    for (int mf = 0; mf < 4; mf++) {
                        uint32_t ah4[4], al4[4];
                        ldsm4(ah4[0], ah4[1], ah4[2], ah4[3],
                              sb + oAh + aoff + (uint32_t)mf * 16 * 208 + ka);
                        ldsm4(al4[0], al4[1], al4[2], al4[3],
                              sb + oAl + aoff + (uint32_t)mf * 16 * 208 + ka);
                        mma_bf16(acc[mf], ah4, bl2);
                        mma_bf16(acc[mf], al4, bh2);
                        mma_bf16(acc[mf], ah4, bh2);
                    }
                }
            }
#pragma unroll
            for (int mf = 0; mf < 4; mf++)
#pragma unroll
                for (int h = 0; h < 2; h++) {
                    int s = mf * 2 + h;
#pragma unroll
                    for (int j = 0; j < 2; j++) {
                        int cl = wid * 8 + 2 * tg + j;
                        float sc = acc[mf][h * 2 + j] - sHNb[cl];
                        int code = ct * 64 + cl;
                        if (sc > best[s] || (sc == best[s] && code < bidx[s])) {
                            best[s] = sc; bidx[s] = code;
                        }
                    }
                }
            __syncthreads();
        }
#pragma unroll
        for (int s = 0; s < 8; s++) {
#pragma unroll
            for (int off = 1; off <= 2; off <<= 1) {
                float os = __shfl_xor_sync(0xffffffffu, best[s], off);
                int   oi = __shfl_xor_sync(0xffffffffu, bidx[s], off);
                if (os > best[s] || (os == best[s] && oi < bidx[s])) {
                    best[s] = os; bidx[s] = oi;
                }
            }
        }
        if (tg == 0) {
#pragma unroll
            for (int mf = 0; mf < 4; mf++)
#pragma unroll
                for (int h = 0; h < 2; h++) {
                    int r = mf * 16 + 8 * h + g;
                    sScore[r * 8 + wid] = best[mf * 2 + h];
                    sIdx[r * 8 + wid]   = bidx[mf * 2 + h];
                }
        }
        __syncthreads();
        if (tid < 64) {
            float bs = -3.0e38f; int bi = 0x7fffffff;
#pragma unroll
            for (int w = 0; w < 8; w++) {
                float s2 = sScore[tid * 8 + w]; int ii = sIdx[tid * 8 + w];
                if (s2 > bs || (s2 == bs && ii < bi)) { bs = s2; bi = ii; }
            }
            sBest[tid] = bi;
        }
        __syncthreads();
        const float* bkb = books + (size_t)k * NEMB * CD;
        for (int e = tid; e < 64 * 96; e += 256) {
            int r = e / 96, d = e - r * 96;
            sRes[r * 97 + d] -= bkb[(size_t)sBest[r] * CD + d];
        }
    }
    __syncthreads();
    for (int e = tid; e < 64 * 96; e += 256) {
        int r = e / 96, d = e - r * 96;
        float v = rD[(size_t)(m0 + r) * CD + d] - sRes[r * 97 + d];
        u16 h, l; split1(v, h, l);
        qh[(size_t)(m0 + r) * CD + d] = h;
        ql[(size_t)(m0 + r) * CD + d] = l;
    }
}

// ---------------- host side ----------------
template<typename T>
static T* sym(const void* s) { void* p = nullptr; cudaGetSymbolAddress(&p, s); return (T*)p; }

static void gemmb(const u16* Ah, const u16* Al, const u16* Bh, const u16* Bl,
                  float* Cm, u16* Chi, u16* Clo,
                  const float* bias, const float* resid,
                  int M, int N, int K, int act, int rmode,
                  const u16* Bh2 = nullptr, const u16* Bl2 = nullptr,
                  float* Cm2 = nullptr,
                  const u16* Ah3 = nullptr, const u16* Al3 = nullptr,
                  const u16* Bh3 = nullptr, const u16* Bl3 = nullptr,
                  float* Cm3 = nullptr, int M3 = 0)
{
    static bool attr = false;
    if (!attr) {
        cudaFuncSetAttribute(gemm_b_k<2>, cudaFuncAttributeMaxDynamicSharedMemorySize,
                             2 * 40960);
        attr = true;
    }
    int zd = Ah3 ? 3 : (Bh2 ? 2 : 1);
    dim3 grid((N + 127) / 128, (M + 127) / 128, zd);
    gemm_b_k<2><<<grid, 256, 2 * 40960>>>(Ah, Al, Bh, Bl, Cm, Chi, Clo, bias, resid,
                                          M, N, K, act, rmode, Bh2, Bl2, Cm2,
                                          Ah3, Al3, Bh3, Bl3, Cm3, M3, 0);
}

static void gemmb4(const u16* Ah, const u16* Al, const u16* Bh, const u16* Bl,
                   float* Cm, u16* Chi, u16* Clo,
                   const float* bias, const float* resid,
                   int M, int N, int K, int act, int rmode, int omode = 0)
{
    static bool attr = false;
    if (!attr) {
        cudaFuncSetAttribute(gemm_b_k<4>, cudaFuncAttributeMaxDynamicSharedMemorySize,
                             4 * 40960);
        attr = true;
    }
    dim3 grid((N + 127) / 128, (M + 127) / 128, 1);
    gemm_b_k<4><<<grid, 256, 4 * 40960>>>(Ah, Al, Bh, Bl, Cm, Chi, Clo, bias, resid,
                                          M, N, K, act, rmode,
                                          nullptr, nullptr, nullptr,
                                          nullptr, nullptr, nullptr, nullptr,
                                          nullptr, 0, omode);
}

extern "C" void kernel_launch(void* const* d_in, const int* in_sizes, int n_in,
                              void* d_out, int out_size)
{
    const float* qa    = (const float*)d_in[0];
    const float* zt    = (const float*)d_in[1];
    const float* lnq_g = (const float*)d_in[2];
    const float* lnq_b = (const float*)d_in[3];
    const float* lnkv_g= (const float*)d_in[4];
    const float* lnkv_b= (const float*)d_in[5];
    const float* Wq    = (const float*)d_in[6];
    const float* Wk    = (const float*)d_in[7];
    const float* Wv    = (const float*)d_in[8];
    const float* Wo    = (const float*)d_in[9];
    const float* ffn_g = (const float*)d_in[10];
    const float* ffn_b = (const float*)d_in[11];
    const float* W1    = (const float*)d_in[12];
    const float* b1    = (const float*)d_in[13];
    const float* W2    = (const float*)d_in[14];
    const float* b2    = (const float*)d_in[15];
    const float* tn_g  = (const float*)d_in[16];
    const float* tn_b  = (const float*)d_in[17];
    const float* scale = (const float*)d_in[18];
    const float* Wd    = (const float*)d_in[19];
    const float* bd    = (const float*)d_in[20];
    const float* Wu    = (const float*)d_in[21];
    const float* bu    = (const float*)d_in[22];
    const float* books = (const float*)d_in[23];
    float* out = (float*)d_out;

    float* p_Qc  = sym<float>(g_Qc);
    float* p_K   = sym<float>(g_K);
    float* p_V   = sym<float>(g_V);
    float* p_y   = sym<float>(g_y);
    float* p_rD  = sym<float>(g_rD);
    float* p_zh  = sym<float>(g_zhat);
    float* p_qln = sym<float>(g_qln);
    float* p_q0  = sym<float>(g_q0);
    float* p_Q0  = sym<float>(g_Q0);
    float* p_y0  = sym<float>(g_y0);
    float* p_rD0 = sym<float>(g_rD0);

    u16* qlh = sym<u16>(u_qlnh); u16* qll = sym<u16>(u_qlnl);
    u16* kvh = sym<u16>(u_kvh);  u16* kvl = sym<u16>(u_kvl);
    u16* cth = sym<u16>(u_ctxh); u16* ctl = sym<u16>(u_ctxl);
    u16* lnh = sym<u16>(u_lnh);  u16* lnl = sym<u16>(u_lnl);
    u16* hh  = sym<u16>(u_hh);   u16* hl  = sym<u16>(u_hl);
    u16* xdh = sym<u16>(u_xdh);  u16* xdl = sym<u16>(u_xdl);
    u16* qdh = sym<u16>(u_qdh);  u16* qdl = sym<u16>(u_qdl);
    u16* q0h = sym<u16>(u_q0h);  u16* q0l = sym<u16>(u_q0l);
    u16* c0h = sym<u16>(u_ctx0h);u16* c0l = sym<u16>(u_ctx0l);
    u16* l0h = sym<u16>(u_ln0h); u16* l0l = sym<u16>(u_ln0l);
    u16* h0h = sym<u16>(u_h0h);  u16* h0l = sym<u16>(u_h0l);
    u16* x0h = sym<u16>(u_xd0h); u16* x0l = sym<u16>(u_xd0l);
    u16* d0h = sym<u16>(u_qd0h); u16* d0l = sym<u16>(u_qd0l);

    u16* wqh = sym<u16>(w_qh); u16* wql = sym<u16>(w_ql);
    u16* wkh = sym<u16>(w_kh); u16* wkl = sym<u16>(w_kl);
    u16* wvh = sym<u16>(w_vh); u16* wvl = sym<u16>(w_vl);
    u16* woh = sym<u16>(w_oh); u16* wol = sym<u16>(w_ol);
    u16* w1h = sym<u16>(w_1h); u16* w1l = sym<u16>(w_1l);
    u16* w2h = sym<u16>(w_2h); u16* w2l = sym<u16>(w_2l);
    u16* wdh = sym<u16>(w_dh); u16* wdl = sym<u16>(w_dl);
    u16* wuh = sym<u16>(w_uh); u16* wul = sym<u16>(w_ul);
    u16* bkh = sym<u16>(bk_h); u16* bkl = sym<u16>(bk_l);

    cudaFuncSetAttribute(rvq_k, cudaFuncAttributeMaxDynamicSharedMemorySize, RVQ_SMEM);

    // ---- prep ----
    prep_splits_k<<<11696, 256>>>(Wq, Wk, Wv, Wo, W1, W2, Wd, Wu, books, lnq_g, lnq_b);
    kvln2_k<<<M2, 256>>>(qa, lnkv_g, lnkv_b);

    // ---- pass A ----
    gemmb(kvh, kvl, wkh, wkl, p_K, nullptr, nullptr, nullptr, nullptr, MR, 512, 512, 0, 0,
          wvh, wvl, p_V,
          qlh, qll, wqh, wql, p_Qc, 16);
    attnA_k<<<M2, 256>>>(p_K, p_V);
    gemmb(cth, ctl, woh, wol, p_y, nullptr, nullptr, nullptr, p_qln, MR, 512, 512, 0, 2);
    ln_rows_k<<<MR, 256>>>(p_y, lnh, lnl, ffn_g, ffn_b);
    gemmb(lnh, lnl, w1h, w1l, nullptr, hh, hl, b1, nullptr, MR, 1024, 512, 1, 0);
    gemmb(hh, hl, w2h, w2l, p_y, nullptr, nullptr, b2, p_y, MR, 512, 1024, 0, 1);
    residA2_k<<<M2, 256>>>(zt, p_y, tn_g, tn_b, scale);
    gemmb(xdh, xdl, wdh, wdl, p_rD, nullptr, nullptr, bd, nullptr, MR, 96, 512, 0, 0);
    rvq_k<<<MR / 64, 256, RVQ_SMEM>>>(p_rD, qdh, qdl, books, bkh, bkl);
    gemmb(qdh, qdl, wuh, wul, p_zh, nullptr, nullptr, bu, p_y, MR, 512, 96, 0, 1);
    scatterA2_k<<<M2, 256>>>(p_zh, out);

    // ---- pass B ----
    q0ln_k<<<M2, 256>>>(lnq_g, lnq_b);
    gemmb4(q0h, q0l, wqh, wql, p_Q0, nullptr, nullptr, nullptr, nullptr, M2, 512, 512, 0, 0);
    attnB_k<<<M2, 256>>>(p_K, p_V);
    gemmb4(c0h, c0l, woh, wol, p_y0, nullptr, nullptr, nullptr, p_q0, M2, 512, 512, 0, 1);
    ln_rows_k<<<M2, 256>>>(p_y0, l0h, l0l, ffn_g, ffn_b);
    gemmb4(l0h, l0l, w1h, w1l, nullptr, h0h, h0l, b1, nullptr, M2, 1024, 512, 1, 0);
    gemmb4(h0h, h0l, w2h, w2l, p_y0, nullptr, nullptr, b2, p_y0, M2, 512, 1024, 0, 1);
    residB_k<<<M2, 256>>>(zt, p_y0, tn_g, tn_b, scale);
    gemmb4(x0h, x0l, wdh, wdl, p_rD0, nullptr, nullptr, bd, nullptr, M2, 96, 512, 0, 0);
    rvq_k<<<M2 / 64, 256, RVQ_SMEM>>>(p_rD0, d0h, d0l, books, bkh, bkl);
    gemmb4(d0h, d0l, wuh, wul, out, nullptr, nullptr, bu, p_y0, M2, 512, 96, 0, 1, 2);
}